// round 5
// baseline (speedup 1.0000x reference)
#include <cuda_runtime.h>
#include <cuda_bf16.h>
#include <math.h>

// ----------------------------------------------------------------------------
// Problem constants
//   src: (B=8, C=64, P=128, D=512) fp32.  NTOK = 65536 tokens.
//   HALF=256, H_HALF=4 heads of HD=64, rope half = 32.
// Key simplification: _attn_residual's softmax is over an axis of size 1 ->
// weights are exactly 1.0 -> res = src @ proj_w.T + proj_b.
// ----------------------------------------------------------------------------
#define NTOK   65536
#define DM     512
#define DFF    2048
#define HALFD  256
#define NB     8
#define NC     64
#define NP     128

// Scratch (device globals: allocation is forbidden in kernel_launch)
__device__ float g_scr0[NTOK * DFF];    // qkv buffer (768 cols) / FFN hidden (2048 cols)
__device__ float g_ln  [NTOK * DM];     // layernorm output
__device__ float g_x2  [NTOK * DM];     // res1 + attention (the mid-block activation)
__device__ float g_ao  [NTOK * HALFD];  // attention context (pre out-proj)
__device__ float g_cos_s[64 * 32];
__device__ float g_sin_s[64 * 32];
__device__ float g_cos_t[128 * 32];
__device__ float g_sin_t[128 * 32];

// ----------------------------------------------------------------------------
// Packed f32x2 helpers (Blackwell FFMA2 — ptxas never emits it from C++)
// ----------------------------------------------------------------------------
__device__ __forceinline__ unsigned long long fma2(unsigned long long a,
                                                   unsigned long long b,
                                                   unsigned long long c) {
    unsigned long long d;
    asm("fma.rn.f32x2 %0, %1, %2, %3;" : "=l"(d) : "l"(a), "l"(b), "l"(c));
    return d;
}
__device__ __forceinline__ unsigned long long dup2(float x) {
    unsigned long long d;
    asm("mov.b64 %0, {%1, %2};" : "=l"(d) : "f"(x), "f"(x));
    return d;
}
__device__ __forceinline__ void unpack2(unsigned long long v, float& lo, float& hi) {
    asm("mov.b64 {%0, %1}, %2;" : "=f"(lo), "=f"(hi) : "l"(v));
}

// ----------------------------------------------------------------------------
// Rope table setup (tiny, one block)
// ----------------------------------------------------------------------------
__global__ void rope_setup_kernel(const float* __restrict__ coords) {
    __shared__ float cx[64], cy[64], cz[64];
    __shared__ float s_inv;
    int t = threadIdx.x;
    if (t == 0) {
        float m0 = 0.f, m1 = 0.f, m2 = 0.f;
        for (int i = 0; i < 64; i++) {
            m0 += coords[3 * i + 0];
            m1 += coords[3 * i + 1];
            m2 += coords[3 * i + 2];
        }
        m0 *= (1.f / 64.f); m1 *= (1.f / 64.f); m2 *= (1.f / 64.f);
        float mx = 0.f;
        for (int i = 0; i < 64; i++) {
            float a = coords[3 * i + 0] - m0;
            float b = coords[3 * i + 1] - m1;
            float c = coords[3 * i + 2] - m2;
            cx[i] = a; cy[i] = b; cz[i] = c;
            float r = sqrtf(a * a + b * b + c * c);
            mx = fmaxf(mx, r);
        }
        s_inv = 1.0f / fmaxf(mx, 1e-6f);
    }
    __syncthreads();
    float inv = s_inv;
    // spatial tables: theta = 2*pi * c[pos, i%3] * freqs[i]
    for (int idx = t; idx < 64 * 32; idx += blockDim.x) {
        int c = idx >> 5, i = idx & 31;
        float fr = powf(10000.0f, -(float)i / 32.0f);
        int ax = i % 3;
        float cv = (ax == 0 ? cx[c] : (ax == 1 ? cy[c] : cz[c])) * inv;
        float th = 6.2831853071795864f * (cv * fr);
        g_cos_s[idx] = cosf(th);
        g_sin_s[idx] = sinf(th);
    }
    // temporal tables: theta = pos * freqs[i]
    for (int idx = t; idx < 128 * 32; idx += blockDim.x) {
        int p = idx >> 5, i = idx & 31;
        float fr = powf(10000.0f, -(float)i / 32.0f);
        float th = (float)p * fr;
        g_cos_t[idx] = cosf(th);
        g_sin_t[idx] = sinf(th);
    }
}

// ----------------------------------------------------------------------------
// LayerNorm: one block per token (512 elems), 128 threads, float4
// ----------------------------------------------------------------------------
__global__ void layernorm_kernel(const float* __restrict__ in,
                                 float* __restrict__ out,
                                 const float* __restrict__ w,
                                 const float* __restrict__ b) {
    int row = blockIdx.x;
    int t = threadIdx.x;  // 128
    const float4* ip = (const float4*)(in + (size_t)row * DM);
    float4 v = ip[t];
    float s = v.x + v.y + v.z + v.w;
    float q = v.x * v.x + v.y * v.y + v.z * v.z + v.w * v.w;
#pragma unroll
    for (int o = 16; o; o >>= 1) {
        s += __shfl_xor_sync(0xffffffffu, s, o);
        q += __shfl_xor_sync(0xffffffffu, q, o);
    }
    __shared__ float ss[4], qq[4];
    if ((t & 31) == 0) { ss[t >> 5] = s; qq[t >> 5] = q; }
    __syncthreads();
    s = ss[0] + ss[1] + ss[2] + ss[3];
    q = qq[0] + qq[1] + qq[2] + qq[3];
    float mean = s * (1.0f / DM);
    float var = q * (1.0f / DM) - mean * mean;
    float rstd = rsqrtf(var + 1e-5f);
    float4 wv = ((const float4*)w)[t];
    float4 bv = ((const float4*)b)[t];
    float4 o;
    o.x = (v.x - mean) * rstd * wv.x + bv.x;
    o.y = (v.y - mean) * rstd * wv.y + bv.y;
    o.z = (v.z - mean) * rstd * wv.z + bv.z;
    o.w = (v.w - mean) * rstd * wv.w + bv.w;
    ((float4*)(out + (size_t)row * DM))[t] = o;
}

// ----------------------------------------------------------------------------
// GEMM: C[M,N] = A[M,K] @ B[N,K]^T (+bias, optional gelu / accumulate)
// AMAP=1: logical row r=(b,p,c) reads physical row (b,c,p)  [spatial gather]
// CMAP=1: logical row r=(b,p,c) writes physical row (b,c,p) [spatial scatter]
// EPI: 0 = store acc+bias; 1 = store gelu(acc+bias); 2 = C += acc+bias
// BM=BN=128, BK=16, 256 threads, 8x8 per thread.
// Inner product uses packed fma.rn.f32x2 (FFMA2): accumulators pair adjacent
// M-rows, A pairs load free from contiguous smem, B is duplicated per column.
// Software-pipelined + double-buffered smem: one __syncthreads per K-tile.
// All dims here are exact multiples of the tile sizes (no bounds checks).
// ----------------------------------------------------------------------------
__device__ __forceinline__ int amap_spatial(int r) {
    // r = b*8192 + p*64 + c  ->  b*8192 + c*128 + p
    int b = r >> 13;
    int p = (r >> 6) & 127;
    int c = r & 63;
    return (b << 13) + (c << 7) + p;
}

__device__ __forceinline__ float gelu_f(float x) {
    return 0.5f * x * (1.0f + erff(x * 0.70710678118654752f));
}

template <int AMAP, int CMAP, int EPI>
__global__ void __launch_bounds__(256, 2) gemm_kernel(
    const float* __restrict__ A, int lda,
    const float* __restrict__ Bw,       // N x K row-major
    const float* __restrict__ bias,     // N
    float* __restrict__ Cp, int ldc,
    int M, int N, int K) {
    const int BM = 128, BN = 128, BK = 16;
    __shared__ float As[2][BK][BM + 4];
    __shared__ float Bs[2][BK][BN + 4];

    int tid = threadIdx.x;
    int row0 = blockIdx.y * BM;
    int col0 = blockIdx.x * BN;

    // loader indices: 512 float4 loads per tile per operand, 2 per thread
    int l0 = tid, l1 = tid + 256;
    int ar0 = l0 >> 2, aq0 = (l0 & 3) << 2;
    int ar1 = l1 >> 2, aq1 = (l1 & 3) << 2;

    size_t aoff0, aoff1;
    {
        int r0 = row0 + ar0;
        int r1 = row0 + ar1;
        if (AMAP == 1) { r0 = amap_spatial(r0); r1 = amap_spatial(r1); }
        aoff0 = (size_t)r0 * lda + aq0;
        aoff1 = (size_t)r1 * lda + aq1;
    }
    size_t boff0 = (size_t)(col0 + ar0) * K + aq0;
    size_t boff1 = (size_t)(col0 + ar1) * K + aq1;

    int tm = (tid >> 4) << 3;
    int tn = (tid & 15) << 3;

    // acc2[ip][j] packs C rows (tm+2ip, tm+2ip+1), column tn+j
    unsigned long long acc2[4][8];
#pragma unroll
    for (int i = 0; i < 4; i++)
#pragma unroll
        for (int j = 0; j < 8; j++) acc2[i][j] = 0ull;  // (0.0f, 0.0f)

    // prefetch tile 0 and commit to buffer 0
    {
        float4 a0 = *(const float4*)(A + aoff0);
        float4 a1 = *(const float4*)(A + aoff1);
        float4 b0 = *(const float4*)(Bw + boff0);
        float4 b1 = *(const float4*)(Bw + boff1);
        As[0][aq0 + 0][ar0] = a0.x; As[0][aq0 + 1][ar0] = a0.y;
        As[0][aq0 + 2][ar0] = a0.z; As[0][aq0 + 3][ar0] = a0.w;
        As[0][aq1 + 0][ar1] = a1.x; As[0][aq1 + 1][ar1] = a1.y;
        As[0][aq1 + 2][ar1] = a1.z; As[0][aq1 + 3][ar1] = a1.w;
        Bs[0][aq0 + 0][ar0] = b0.x; Bs[0][aq0 + 1][ar0] = b0.y;
        Bs[0][aq0 + 2][ar0] = b0.z; Bs[0][aq0 + 3][ar0] = b0.w;
        Bs[0][aq1 + 0][ar1] = b1.x; Bs[0][aq1 + 1][ar1] = b1.y;
        Bs[0][aq1 + 2][ar1] = b1.z; Bs[0][aq1 + 3][ar1] = b1.w;
    }
    __syncthreads();

    int cur = 0;
    for (int k0 = 0; k0 < K; k0 += BK) {
        int kn = k0 + BK;
        bool has_next = (kn < K);
        float4 a0, a1, b0, b1;
        if (has_next) {
            // issue next tile's global loads; latency hides under FMAs below
            a0 = *(const float4*)(A + aoff0 + kn);
            a1 = *(const float4*)(A + aoff1 + kn);
            b0 = *(const float4*)(Bw + boff0 + kn);
            b1 = *(const float4*)(Bw + boff1 + kn);
        }
#pragma unroll
        for (int kk = 0; kk < BK; kk++) {
            // A pairs: contiguous & 16B-aligned (row stride 132 floats = 528B,
            // multiple of 16; tm is a multiple of 8) -> free ulonglong2 loads.
            ulonglong2 ap0 = *(const ulonglong2*)&As[cur][kk][tm];
            ulonglong2 ap1 = *(const ulonglong2*)&As[cur][kk][tm + 4];
            unsigned long long a2[4] = {ap0.x, ap0.y, ap1.x, ap1.y};
            float4 bv0 = *(const float4*)&Bs[cur][kk][tn];
            float4 bv1 = *(const float4*)&Bs[cur][kk][tn + 4];
            unsigned long long bd[8];
            bd[0] = dup2(bv0.x); bd[1] = dup2(bv0.y);
            bd[2] = dup2(bv0.z); bd[3] = dup2(bv0.w);
            bd[4] = dup2(bv1.x); bd[5] = dup2(bv1.y);
            bd[6] = dup2(bv1.z); bd[7] = dup2(bv1.w);
#pragma unroll
            for (int ip = 0; ip < 4; ip++)
#pragma unroll
                for (int j = 0; j < 8; j++)
                    acc2[ip][j] = fma2(a2[ip], bd[j], acc2[ip][j]);
        }
        if (has_next) {
            int nxt = cur ^ 1;
            // nxt buffer was last READ before the barrier of the previous
            // iteration -> safe to overwrite now.
            As[nxt][aq0 + 0][ar0] = a0.x; As[nxt][aq0 + 1][ar0] = a0.y;
            As[nxt][aq0 + 2][ar0] = a0.z; As[nxt][aq0 + 3][ar0] = a0.w;
            As[nxt][aq1 + 0][ar1] = a1.x; As[nxt][aq1 + 1][ar1] = a1.y;
            As[nxt][aq1 + 2][ar1] = a1.z; As[nxt][aq1 + 3][ar1] = a1.w;
            Bs[nxt][aq0 + 0][ar0] = b0.x; Bs[nxt][aq0 + 1][ar0] = b0.y;
            Bs[nxt][aq0 + 2][ar0] = b0.z; Bs[nxt][aq0 + 3][ar0] = b0.w;
            Bs[nxt][aq1 + 0][ar1] = b1.x; Bs[nxt][aq1 + 1][ar1] = b1.y;
            Bs[nxt][aq1 + 2][ar1] = b1.z; Bs[nxt][aq1 + 3][ar1] = b1.w;
            __syncthreads();
        }
        cur ^= 1;
    }

    // unpack pairs -> scalar acc rows, then audited epilogue
    float acc[8][8];
#pragma unroll
    for (int ip = 0; ip < 4; ip++)
#pragma unroll
        for (int j = 0; j < 8; j++)
            unpack2(acc2[ip][j], acc[2 * ip][j], acc[2 * ip + 1][j]);

#pragma unroll
    for (int i = 0; i < 8; i++) {
        int r = row0 + tm + i;
        int orow = (CMAP == 1) ? amap_spatial(r) : r;
        float* cptr = Cp + (size_t)orow * ldc + col0 + tn;
#pragma unroll
        for (int j = 0; j < 8; j += 4) {
            float4 bb = *(const float4*)(bias + col0 + tn + j);
            float4 vv;
            vv.x = acc[i][j + 0] + bb.x;
            vv.y = acc[i][j + 1] + bb.y;
            vv.z = acc[i][j + 2] + bb.z;
            vv.w = acc[i][j + 3] + bb.w;
            if (EPI == 1) {
                vv.x = gelu_f(vv.x); vv.y = gelu_f(vv.y);
                vv.z = gelu_f(vv.z); vv.w = gelu_f(vv.w);
            }
            if (EPI == 2) {
                float4 old = *(const float4*)(cptr + j);
                vv.x += old.x; vv.y += old.y; vv.z += old.z; vv.w += old.w;
            }
            *(float4*)(cptr + j) = vv;
        }
    }
}

// ----------------------------------------------------------------------------
// Attention: one block handles 64 queries of one (batch, head) against all L
// keys. Rope fused on q/k load. qkv buffer rows: [batch*L + pos] x 768
// (q cols h*64.., k cols 256+h*64.., v cols 512+h*64..).
// Output written to g_ao rows [batch*L + pos], cols h*64..
// grid = (nBatch, 4, L/64), 256 threads.
// QK and PV inner loops use packed fma.rn.f32x2 (pairs of adjacent dims).
// ----------------------------------------------------------------------------
template <int L>
__global__ void attn_kernel(const float* __restrict__ qkv,
                            const float* __restrict__ cosT,
                            const float* __restrict__ sinT,
                            float* __restrict__ outp) {
    extern __shared__ float sm[];
    float* qr = sm;                 // 64*64
    float* kr = qr + 64 * 64;       // L*64
    float* vs = kr + L * 64;        // L*64
    float* sc = vs + L * 64;        // 64*L

    int batch = blockIdx.x;
    int h = blockIdx.y;
    int qc = blockIdx.z;
    int t = threadIdx.x;  // 256
    size_t base = (size_t)batch * L;
    const float* qkvb = qkv + base * 768;

    // K with rope
    for (int idx = t; idx < L * 32; idx += 256) {
        int j = idx >> 5, d = idx & 31;
        const float* rowp = qkvb + (size_t)j * 768 + 256 + h * 64;
        float k1 = rowp[d], k2 = rowp[d + 32];
        float co = cosT[(j << 5) + d], si = sinT[(j << 5) + d];
        kr[(j << 6) + d]      = k1 * co - k2 * si;
        kr[(j << 6) + d + 32] = k1 * si + k2 * co;
    }
    // V
    for (int idx = t; idx < L * 64; idx += 256) {
        int j = idx >> 6, d = idx & 63;
        vs[idx] = qkvb[(size_t)j * 768 + 512 + h * 64 + d];
    }
    // Q chunk with rope
    for (int idx = t; idx < 64 * 32; idx += 256) {
        int i = idx >> 5, d = idx & 31;
        int qi = qc * 64 + i;
        const float* rowp = qkvb + (size_t)qi * 768 + h * 64;
        float q1 = rowp[d], q2 = rowp[d + 32];
        float co = cosT[(qi << 5) + d], si = sinT[(qi << 5) + d];
        qr[(i << 6) + d]      = q1 * co - q2 * si;
        qr[(i << 6) + d + 32] = q1 * si + q2 * co;
    }
    __syncthreads();

    const int JP = L / 4;
    int i = t >> 2;
    int part = t & 3;

    // cache q row in registers as 32 packed f32x2 pairs (rows are 256B-aligned)
    unsigned long long q2[32];
    {
        const ulonglong2* qrow = (const ulonglong2*)(qr + (i << 6));
#pragma unroll
        for (int u = 0; u < 16; u++) {
            ulonglong2 p = qrow[u];
            q2[2 * u] = p.x;
            q2[2 * u + 1] = p.y;
        }
    }

    float svals[JP];
    float mx = -1e30f;
#pragma unroll 4
    for (int jj = 0; jj < JP; jj++) {
        int j = part * JP + jj;
        const ulonglong2* krow = (const ulonglong2*)(kr + (j << 6));
        unsigned long long s2 = 0ull;
#pragma unroll
        for (int u = 0; u < 16; u++) {
            ulonglong2 kp = krow[u];
            s2 = fma2(q2[2 * u], kp.x, s2);
            s2 = fma2(q2[2 * u + 1], kp.y, s2);
        }
        float slo, shi;
        unpack2(s2, slo, shi);
        float s = (slo + shi) * 0.125f;  // 1/sqrt(64)
        svals[jj] = s;
        mx = fmaxf(mx, s);
    }
    mx = fmaxf(mx, __shfl_xor_sync(0xffffffffu, mx, 1));
    mx = fmaxf(mx, __shfl_xor_sync(0xffffffffu, mx, 2));
    float sum = 0.f;
#pragma unroll 4
    for (int jj = 0; jj < JP; jj++) {
        float e = __expf(svals[jj] - mx);
        svals[jj] = e;
        sum += e;
    }
    sum += __shfl_xor_sync(0xffffffffu, sum, 1);
    sum += __shfl_xor_sync(0xffffffffu, sum, 2);
    float invs = 1.0f / sum;
#pragma unroll 4
    for (int jj = 0; jj < JP; jj++) sc[i * L + part * JP + jj] = svals[jj] * invs;
    __syncthreads();

    // out[i][d0..d0+15] = sum_j p[i][j] * v[j][d]  (8 packed pairs per thread)
    int d0 = part << 4;  // multiple of 16 floats -> 64B-aligned slices
    unsigned long long acc2[8];
#pragma unroll
    for (int u = 0; u < 8; u++) acc2[u] = 0ull;
    for (int j = 0; j < L; j++) {
        unsigned long long pd = dup2(sc[i * L + j]);
        const ulonglong2* vrow = (const ulonglong2*)(vs + (j << 6) + d0);
#pragma unroll
        for (int u = 0; u < 4; u++) {
            ulonglong2 vp = vrow[u];
            acc2[2 * u] = fma2(pd, vp.x, acc2[2 * u]);
            acc2[2 * u + 1] = fma2(pd, vp.y, acc2[2 * u + 1]);
        }
    }
    float* op = outp + (base + (size_t)qc * 64 + i) * 256 + h * 64 + d0;
#pragma unroll
    for (int u = 0; u < 4; u++) {
        float4 vv;
        unpack2(acc2[2 * u], vv.x, vv.y);
        unpack2(acc2[2 * u + 1], vv.z, vv.w);
        ((float4*)op)[u] = vv;
    }
}

// ----------------------------------------------------------------------------
// Launch
// ----------------------------------------------------------------------------
extern "C" void kernel_launch(void* const* d_in, const int* in_sizes, int n_in,
                              void* d_out, int out_size) {
    const float* src         = (const float*)d_in[0];
    const float* coords      = (const float*)d_in[1];
    // d_in[2] q_attn, d_in[3] rms_attn: dead (softmax over size-1 axis == 1)
    const float* proj_attn_w = (const float*)d_in[4];
    const float* proj_attn_b = (const float*)d_in[5];
    // d_in[6] q_ffn, d_in[7] rms_ffn: dead
    const float* proj_ffn_w  = (const float*)d_in[8];
    const float* proj_ffn_b  = (const float*)d_in[9];
    const float* ln1_w = (const float*)d_in[10];
    const float* ln1_b = (const float*)d_in[11];
    const float* ln2_w = (const float*)d_in[12];
    const float* ln2_b = (const float*)d_in[13];
    const float* qkv_s_w = (const float*)d_in[14];
    const float* qkv_s_b = (const float*)d_in[15];
    const float* out_s_w = (const float*)d_in[16];
    const float* out_s_b = (const float*)d_in[17];
    const float* qkv_t_w = (const float*)d_in[18];
    const float* qkv_t_b = (const float*)d_in[19];
    const float* out_t_w = (const float*)d_in[20];
    const float* out_t_b = (const float*)d_in[21];
    const float* w1 = (const float*)d_in[22];
    const float* b1 = (const float*)d_in[23];
    const float* w2 = (const float*)d_in[24];
    const float* b2 = (const float*)d_in[25];
    float* out = (float*)d_out;

    float *scr0, *ln, *x2, *ao, *cs, *sn, *ct, *st;
    cudaGetSymbolAddress((void**)&scr0, g_scr0);
    cudaGetSymbolAddress((void**)&ln, g_ln);
    cudaGetSymbolAddress((void**)&x2, g_x2);
    cudaGetSymbolAddress((void**)&ao, g_ao);
    cudaGetSymbolAddress((void**)&cs, g_cos_s);
    cudaGetSymbolAddress((void**)&sn, g_sin_s);
    cudaGetSymbolAddress((void**)&ct, g_cos_t);
    cudaGetSymbolAddress((void**)&st, g_sin_t);

    // dynamic smem sizes for attention (idempotent; capture-safe)
    const int smem64 = (64 * 64 + 64 * 64 * 2 + 64 * 64) * 4;            // 64 KB
    const int smem128 = (64 * 64 + 128 * 64 * 2 + 64 * 128) * 4;         // 112 KB
    cudaFuncSetAttribute((const void*)attn_kernel<64>,
                         cudaFuncAttributeMaxDynamicSharedMemorySize, smem64);
    cudaFuncSetAttribute((const void*)attn_kernel<128>,
                         cudaFuncAttributeMaxDynamicSharedMemorySize, smem128);

    // 0. rope tables
    rope_setup_kernel<<<1, 128>>>(coords);

    // 1. LN1: src -> g_ln
    layernorm_kernel<<<NTOK, 128>>>(src, ln, ln1_w, ln1_b);

    // 2. res1 = src @ proj_attn_w^T + b -> g_x2
    gemm_kernel<0, 0, 0><<<dim3(DM / 128, NTOK / 128), 256>>>(
        src, DM, proj_attn_w, proj_attn_b, x2, DM, NTOK, DM, DM);

    // 3. qkv_s = gather_spatial(g_ln[:, :256]) @ qkv_s_w^T + b -> g_scr0 (768)
    gemm_kernel<1, 0, 0><<<dim3(768 / 128, NTOK / 128), 256>>>(
        ln, DM, qkv_s_w, qkv_s_b, scr0, 768, NTOK, 768, HALFD);

    // 4. spatial attention (L=64, 1024 batches, 4 heads) -> g_ao
    attn_kernel<64><<<dim3(NB * NP, 4, 1), 256, smem64>>>(scr0, cs, sn, ao);

    // 5. out-proj spatial: g_x2[:, :256] += scatter(g_ao @ out_s_w^T + b)
    gemm_kernel<0, 1, 2><<<dim3(HALFD / 128, NTOK / 128), 256>>>(
        ao, HALFD, out_s_w, out_s_b, x2, DM, NTOK, HALFD, HALFD);

    // 6. qkv_t = g_ln[:, 256:] @ qkv_t_w^T + b -> g_scr0
    gemm_kernel<0, 0, 0><<<dim3(768 / 128, NTOK / 128), 256>>>(
        ln + HALFD, DM, qkv_t_w, qkv_t_b, scr0, 768, NTOK, 768, HALFD);

    // 7. temporal attention (L=128, 512 batches, 4 heads, 2 query chunks)
    attn_kernel<128><<<dim3(NB * NC, 4, 2), 256, smem128>>>(scr0, ct, st, ao);

    // 8. out-proj temporal: g_x2[:, 256:] += g_ao @ out_t_w^T + b
    gemm_kernel<0, 0, 2><<<dim3(HALFD / 128, NTOK / 128), 256>>>(
        ao, HALFD, out_t_w, out_t_b, x2 + HALFD, DM, NTOK, HALFD, HALFD);

    // 9. LN2: g_x2 -> g_ln
    layernorm_kernel<<<NTOK, 128>>>(x2, ln, ln2_w, ln2_b);

    // 10. res2 = g_x2 @ proj_ffn_w^T + b -> out
    gemm_kernel<0, 0, 0><<<dim3(DM / 128, NTOK / 128), 256>>>(
        x2, DM, proj_ffn_w, proj_ffn_b, out, DM, NTOK, DM, DM);

    // 11. ff1 = gelu(g_ln @ w1^T + b1) -> g_scr0 (2048)
    gemm_kernel<0, 0, 1><<<dim3(DFF / 128, NTOK / 128), 256>>>(
        ln, DM, w1, b1, scr0, DFF, NTOK, DFF, DM);

    // 12. out += g_scr0 @ w2^T + b2
    gemm_kernel<0, 0, 2><<<dim3(DM / 128, NTOK / 128), 256>>>(
        scr0, DFF, w2, b2, out, DM, NTOK, DM, DFF);
}

// round 14
// speedup vs baseline: 1.6599x; 1.6599x over previous
#include <cuda_runtime.h>
#include <cuda_bf16.h>
#include <math.h>
#include <stdint.h>

// ----------------------------------------------------------------------------
// Problem constants
//   src: (B=8, C=64, P=128, D=512) fp32.  NTOK = 65536 tokens.
//   HALF=256, H_HALF=4 heads of HD=64, rope half = 32.
// Key simplification: _attn_residual's softmax is over an axis of size 1 ->
// weights are exactly 1.0 -> res = src @ proj_w.T + proj_b.
//
// GEMM strategy: split-bf16 tensor-core GEMM (mma.sync.m16n8k16) for ALL
// GEMMs, including the spatially-permuted pair (AMAP row-gather on A,
// CMAP row-scatter on C). x = hi + lo (bf16),
// C = Ahi*Bhi + Ahi*Blo + Alo*Bhi (fp32 accum, ~1e-5 rel).
// ----------------------------------------------------------------------------
#define NTOK   65536
#define DM     512
#define DFF    2048
#define HALFD  256
#define NB     8
#define NC     64
#define NP     128

// fp32 scratch
__device__ float g_scr0[NTOK * 768];    // qkv buffer fp32
__device__ float g_ln  [NTOK * DM];     // layernorm output fp32
__device__ float g_x2  [NTOK * DM];     // mid-block activation fp32
__device__ float g_ao  [NTOK * HALFD];  // attention context fp32
__device__ float g_cos_s[64 * 32];
__device__ float g_sin_s[64 * 32];
__device__ float g_cos_t[128 * 32];
__device__ float g_sin_t[128 * 32];
// bf16 hi/lo scratch (A-side operands) — 256B-aligned: cp.async 16B copies
// require 16B-aligned global addresses; bf16 arrays only guarantee 2B by type.
__device__ __align__(256) __nv_bfloat16 g_srch[NTOK * DM];
__device__ __align__(256) __nv_bfloat16 g_srcl[NTOK * DM];
__device__ __align__(256) __nv_bfloat16 g_lnh [NTOK * DM];
__device__ __align__(256) __nv_bfloat16 g_lnl [NTOK * DM];
__device__ __align__(256) __nv_bfloat16 g_x2h [NTOK * DM];
__device__ __align__(256) __nv_bfloat16 g_x2l [NTOK * DM];
__device__ __align__(256) __nv_bfloat16 g_aoh [NTOK * HALFD];
__device__ __align__(256) __nv_bfloat16 g_aol [NTOK * HALFD];
__device__ __align__(256) __nv_bfloat16 g_ffh [NTOK * DFF];
__device__ __align__(256) __nv_bfloat16 g_ffl [NTOK * DFF];
// bf16 hi/lo weight pool
#define WOFF_PA 0
#define WOFF_PF (WOFF_PA + DM * DM)
#define WOFF_QT (WOFF_PF + DM * DM)
#define WOFF_OT (WOFF_QT + 768 * HALFD)
#define WOFF_W1 (WOFF_OT + HALFD * HALFD)
#define WOFF_W2 (WOFF_W1 + DFF * DM)
#define WOFF_QS (WOFF_W2 + DM * DFF)
#define WOFF_OS (WOFF_QS + 768 * HALFD)
#define WPOOL   (WOFF_OS + HALFD * HALFD)
__device__ __align__(256) __nv_bfloat16 g_wh[WPOOL];
__device__ __align__(256) __nv_bfloat16 g_wl[WPOOL];

// ----------------------------------------------------------------------------
// Packed f32x2 helpers (FFMA2) — used by attention
// ----------------------------------------------------------------------------
__device__ __forceinline__ unsigned long long fma2(unsigned long long a,
                                                   unsigned long long b,
                                                   unsigned long long c) {
    unsigned long long d;
    asm("fma.rn.f32x2 %0, %1, %2, %3;" : "=l"(d) : "l"(a), "l"(b), "l"(c));
    return d;
}
__device__ __forceinline__ unsigned long long dup2(float x) {
    unsigned long long d;
    asm("mov.b64 %0, {%1, %2};" : "=l"(d) : "f"(x), "f"(x));
    return d;
}
__device__ __forceinline__ void unpack2(unsigned long long v, float& lo, float& hi) {
    asm("mov.b64 {%0, %1}, %2;" : "=f"(lo), "=f"(hi) : "l"(v));
}

// ----------------------------------------------------------------------------
// Tensor-core helpers
// ----------------------------------------------------------------------------
__device__ __forceinline__ void mma_bf16(float* c, uint32_t a0, uint32_t a1,
                                         uint32_t a2, uint32_t a3,
                                         uint32_t b0, uint32_t b1) {
    asm volatile(
        "mma.sync.aligned.m16n8k16.row.col.f32.bf16.bf16.f32 "
        "{%0,%1,%2,%3}, {%4,%5,%6,%7}, {%8,%9}, {%0,%1,%2,%3};"
        : "+f"(c[0]), "+f"(c[1]), "+f"(c[2]), "+f"(c[3])
        : "r"(a0), "r"(a1), "r"(a2), "r"(a3), "r"(b0), "r"(b1));
}
__device__ __forceinline__ void ldmx4(uint32_t* r, uint32_t addr) {
    asm volatile("ldmatrix.sync.aligned.m8n8.x4.shared.b16 {%0,%1,%2,%3}, [%4];"
                 : "=r"(r[0]), "=r"(r[1]), "=r"(r[2]), "=r"(r[3]) : "r"(addr));
}
__device__ __forceinline__ void cpasync16(uint32_t dst, const void* src) {
    asm volatile("cp.async.cg.shared.global [%0], [%1], 16;"
                 :: "r"(dst), "l"(src));
}

__device__ __forceinline__ void split_hl(float x, __nv_bfloat16& h, __nv_bfloat16& l) {
    h = __float2bfloat16_rn(x);
    l = __float2bfloat16_rn(x - __bfloat162float(h));
}

// spatial permutation: logical row r=(b,p,c) <-> physical row (b,c,p)
__device__ __forceinline__ int amap_spatial(int r) {
    int b = r >> 13;
    int p = (r >> 6) & 127;
    int c = r & 63;
    return (b << 13) + (c << 7) + p;
}

// ----------------------------------------------------------------------------
// fp32 -> bf16 hi/lo converter (grid-stride, float4 granularity)
// ----------------------------------------------------------------------------
__global__ void convert_hl_kernel(const float* __restrict__ in,
                                  __nv_bfloat16* __restrict__ h,
                                  __nv_bfloat16* __restrict__ l, int n4) {
    for (int i = blockIdx.x * blockDim.x + threadIdx.x; i < n4;
         i += gridDim.x * blockDim.x) {
        float4 v = ((const float4*)in)[i];
        __nv_bfloat162 h0, h1, l0, l1;
        split_hl(v.x, h0.x, l0.x);
        split_hl(v.y, h0.y, l0.y);
        split_hl(v.z, h1.x, l1.x);
        split_hl(v.w, h1.y, l1.y);
        ((__nv_bfloat162*)h)[2 * i] = h0;
        ((__nv_bfloat162*)h)[2 * i + 1] = h1;
        ((__nv_bfloat162*)l)[2 * i] = l0;
        ((__nv_bfloat162*)l)[2 * i + 1] = l1;
    }
}

// ----------------------------------------------------------------------------
// Rope table setup (tiny, one block)
// ----------------------------------------------------------------------------
__global__ void rope_setup_kernel(const float* __restrict__ coords) {
    __shared__ float cx[64], cy[64], cz[64];
    __shared__ float s_inv;
    int t = threadIdx.x;
    if (t == 0) {
        float m0 = 0.f, m1 = 0.f, m2 = 0.f;
        for (int i = 0; i < 64; i++) {
            m0 += coords[3 * i + 0];
            m1 += coords[3 * i + 1];
            m2 += coords[3 * i + 2];
        }
        m0 *= (1.f / 64.f); m1 *= (1.f / 64.f); m2 *= (1.f / 64.f);
        float mx = 0.f;
        for (int i = 0; i < 64; i++) {
            float a = coords[3 * i + 0] - m0;
            float b = coords[3 * i + 1] - m1;
            float c = coords[3 * i + 2] - m2;
            cx[i] = a; cy[i] = b; cz[i] = c;
            float r = sqrtf(a * a + b * b + c * c);
            mx = fmaxf(mx, r);
        }
        s_inv = 1.0f / fmaxf(mx, 1e-6f);
    }
    __syncthreads();
    float inv = s_inv;
    for (int idx = t; idx < 64 * 32; idx += blockDim.x) {
        int c = idx >> 5, i = idx & 31;
        float fr = powf(10000.0f, -(float)i / 32.0f);
        int ax = i % 3;
        float cv = (ax == 0 ? cx[c] : (ax == 1 ? cy[c] : cz[c])) * inv;
        float th = 6.2831853071795864f * (cv * fr);
        g_cos_s[idx] = cosf(th);
        g_sin_s[idx] = sinf(th);
    }
    for (int idx = t; idx < 128 * 32; idx += blockDim.x) {
        int p = idx >> 5, i = idx & 31;
        float fr = powf(10000.0f, -(float)i / 32.0f);
        float th = (float)p * fr;
        g_cos_t[idx] = cosf(th);
        g_sin_t[idx] = sinf(th);
    }
}

// ----------------------------------------------------------------------------
// LayerNorm fused with bf16 hi/lo emission
// ----------------------------------------------------------------------------
__global__ void layernorm_kernel(const float* __restrict__ in,
                                 float* __restrict__ out,
                                 __nv_bfloat16* __restrict__ oh,
                                 __nv_bfloat16* __restrict__ ol,
                                 const float* __restrict__ w,
                                 const float* __restrict__ b) {
    int row = blockIdx.x;
    int t = threadIdx.x;  // 128
    const float4* ip = (const float4*)(in + (size_t)row * DM);
    float4 v = ip[t];
    float s = v.x + v.y + v.z + v.w;
    float q = v.x * v.x + v.y * v.y + v.z * v.z + v.w * v.w;
#pragma unroll
    for (int o = 16; o; o >>= 1) {
        s += __shfl_xor_sync(0xffffffffu, s, o);
        q += __shfl_xor_sync(0xffffffffu, q, o);
    }
    __shared__ float ss[4], qq[4];
    if ((t & 31) == 0) { ss[t >> 5] = s; qq[t >> 5] = q; }
    __syncthreads();
    s = ss[0] + ss[1] + ss[2] + ss[3];
    q = qq[0] + qq[1] + qq[2] + qq[3];
    float mean = s * (1.0f / DM);
    float var = q * (1.0f / DM) - mean * mean;
    float rstd = rsqrtf(var + 1e-5f);
    float4 wv = ((const float4*)w)[t];
    float4 bv = ((const float4*)b)[t];
    float4 o;
    o.x = (v.x - mean) * rstd * wv.x + bv.x;
    o.y = (v.y - mean) * rstd * wv.y + bv.y;
    o.z = (v.z - mean) * rstd * wv.z + bv.z;
    o.w = (v.w - mean) * rstd * wv.w + bv.w;
    ((float4*)(out + (size_t)row * DM))[t] = o;
    __nv_bfloat162 ph, pl;
    __nv_bfloat162* hp = (__nv_bfloat162*)(oh + (size_t)row * DM) + 2 * t;
    __nv_bfloat162* lp = (__nv_bfloat162*)(ol + (size_t)row * DM) + 2 * t;
    split_hl(o.x, ph.x, pl.x); split_hl(o.y, ph.y, pl.y);
    hp[0] = ph; lp[0] = pl;
    split_hl(o.z, ph.x, pl.x); split_hl(o.w, ph.y, pl.y);
    hp[1] = ph; lp[1] = pl;
}

// ----------------------------------------------------------------------------
// Split-bf16 tensor-core GEMM: C[M,N] = (Ah+Al)[M,K] @ (Bh+Bl)[N,K]^T + bias
// EPI: 0 = store fp32; 1 = gelu, store bf16 hi/lo (Chp/Clp); 2 = fp32 +=
// AMAP=1: A logical row r reads physical row amap_spatial(r)  [gather]
// CMAP=1: C logical row r writes physical row amap_spatial(r) [scatter]
// BM=BN=128, BK=32, 256 threads (8 warps, 2x4), warp tile 64x32.
// smem: 4 matrices (Ah,Al,Bh,Bl) x 2 buffers, row stride 40 bf16 (80B):
// ldmatrix phases hit all 32 banks once; B LDS.32 conflict-free.
// cp.async double-buffer, depth 2.
// ----------------------------------------------------------------------------
template <int EPI, int AMAP, int CMAP>
__global__ void __launch_bounds__(256, 2) mma_gemm_kernel(
    const __nv_bfloat16* __restrict__ Ahp, const __nv_bfloat16* __restrict__ Alp,
    int lda,
    const __nv_bfloat16* __restrict__ Bhp, const __nv_bfloat16* __restrict__ Blp,
    const float* __restrict__ bias,
    float* __restrict__ Cp,
    __nv_bfloat16* __restrict__ Chp, __nv_bfloat16* __restrict__ Clp,
    int ldc, int N, int K) {
    const int TS = 128 * 40;          // elements per matrix per buffer
    const uint32_t MATB = TS * 2;     // bytes per matrix-buffer
    extern __shared__ __nv_bfloat16 smem[];
    __nv_bfloat16* sBh = smem + 4 * TS;   // matrix index 2
    __nv_bfloat16* sBl = smem + 6 * TS;   // matrix index 3

    int tid = threadIdx.x;
    int row0 = blockIdx.y * 128, col0 = blockIdx.x * 128;
    int lr = tid >> 1, lh = tid & 1;
    int arow = row0 + lr;
    if (AMAP == 1) arow = amap_spatial(arow);
    const __nv_bfloat16* gAh = Ahp + (size_t)arow * lda + lh * 16;
    const __nv_bfloat16* gAl = Alp + (size_t)arow * lda + lh * 16;
    const __nv_bfloat16* gBh = Bhp + (size_t)(col0 + lr) * K + lh * 16;
    const __nv_bfloat16* gBl = Blp + (size_t)(col0 + lr) * K + lh * 16;
    uint32_t smem_b = (uint32_t)__cvta_generic_to_shared(smem);
    uint32_t ldoff = (uint32_t)(lr * 40 + lh * 16) * 2;

    int wid = tid >> 5, lane = tid & 31;
    int wm = (wid >> 2) * 64, wn = (wid & 3) * 32;
    int g = lane >> 2, tig = lane & 3;

    float acc[4][4][4];
#pragma unroll
    for (int mt = 0; mt < 4; mt++)
#pragma unroll
        for (int nt = 0; nt < 4; nt++)
#pragma unroll
            for (int u = 0; u < 4; u++) acc[mt][nt][u] = 0.f;

    auto issue_tile = [&](int t, int b) {
        int kt = t * 32;
        uint32_t o = ldoff + (uint32_t)b * MATB;
        cpasync16(smem_b + 0 * 2 * MATB + o,      gAh + kt);
        cpasync16(smem_b + 0 * 2 * MATB + o + 16, gAh + kt + 8);
        cpasync16(smem_b + 1 * 2 * MATB + o,      gAl + kt);
        cpasync16(smem_b + 1 * 2 * MATB + o + 16, gAl + kt + 8);
        cpasync16(smem_b + 2 * 2 * MATB + o,      gBh + kt);
        cpasync16(smem_b + 2 * 2 * MATB + o + 16, gBh + kt + 8);
        cpasync16(smem_b + 3 * 2 * MATB + o,      gBl + kt);
        cpasync16(smem_b + 3 * 2 * MATB + o + 16, gBl + kt + 8);
        asm volatile("cp.async.commit_group;");
    };

    int T = K / 32;
    issue_tile(0, 0);
    for (int t = 0; t < T; t++) {
        int b = t & 1;
        if (t + 1 < T) {
            issue_tile(t + 1, b ^ 1);
            asm volatile("cp.async.wait_group 1;");
        } else {
            asm volatile("cp.async.wait_group 0;");
        }
        __syncthreads();
        // compute on buffer b
        const uint32_t aHbase = smem_b + (uint32_t)(0 * 2 + b) * MATB;
        const uint32_t aLbase = smem_b + (uint32_t)(1 * 2 + b) * MATB;
        const __nv_bfloat16* bh = sBh + b * TS;
        const __nv_bfloat16* bl = sBl + b * TS;
#pragma unroll
        for (int ks = 0; ks < 2; ks++) {
            int k0 = ks * 16;
            uint32_t Bh_[4][2], Bl_[4][2];
#pragma unroll
            for (int nt = 0; nt < 4; nt++) {
                const __nv_bfloat16* ph = bh + (wn + nt * 8 + g) * 40 + k0 + 2 * tig;
                const __nv_bfloat16* pl = bl + (wn + nt * 8 + g) * 40 + k0 + 2 * tig;
                Bh_[nt][0] = *(const uint32_t*)ph;
                Bh_[nt][1] = *(const uint32_t*)(ph + 8);
                Bl_[nt][0] = *(const uint32_t*)pl;
                Bl_[nt][1] = *(const uint32_t*)(pl + 8);
            }
#pragma unroll
            for (int mt = 0; mt < 4; mt++) {
                int r = wm + mt * 16 + (lane & 15);
                uint32_t off = (uint32_t)(r * 40 + k0 + ((lane >> 4) << 3)) * 2;
                uint32_t ah[4], al[4];
                ldmx4(ah, aHbase + off);
                ldmx4(al, aLbase + off);
#pragma unroll
                for (int nt = 0; nt < 4; nt++) {
                    mma_bf16(acc[mt][nt], ah[0], ah[1], ah[2], ah[3],
                             Bh_[nt][0], Bh_[nt][1]);
                    mma_bf16(acc[mt][nt], ah[0], ah[1], ah[2], ah[3],
                             Bl_[nt][0], Bl_[nt][1]);
                    mma_bf16(acc[mt][nt], al[0], al[1], al[2], al[3],
                             Bh_[nt][0], Bh_[nt][1]);
                }
            }
        }
        __syncthreads();
    }

    // epilogue: each thread owns rows {rb, rb+8}, cols {cb, cb+1} per tile
#pragma unroll
    for (int mt = 0; mt < 4; mt++) {
#pragma unroll
        for (int nt = 0; nt < 4; nt++) {
            int rb = row0 + wm + mt * 16 + g;
            int r0o = (CMAP == 1) ? amap_spatial(rb) : rb;
            int r1o = (CMAP == 1) ? amap_spatial(rb + 8) : rb + 8;
            int cb = col0 + wn + nt * 8 + 2 * tig;
            float2 bv = *(const float2*)(bias + cb);
            float v0 = acc[mt][nt][0] + bv.x;
            float v1 = acc[mt][nt][1] + bv.y;
            float v2 = acc[mt][nt][2] + bv.x;
            float v3 = acc[mt][nt][3] + bv.y;
            if (EPI == 1) {
                v0 = 0.5f * v0 * (1.0f + erff(v0 * 0.70710678118654752f));
                v1 = 0.5f * v1 * (1.0f + erff(v1 * 0.70710678118654752f));
                v2 = 0.5f * v2 * (1.0f + erff(v2 * 0.70710678118654752f));
                v3 = 0.5f * v3 * (1.0f + erff(v3 * 0.70710678118654752f));
                __nv_bfloat162 ph, pl;
                split_hl(v0, ph.x, pl.x); split_hl(v1, ph.y, pl.y);
                *(__nv_bfloat162*)(Chp + (size_t)r0o * ldc + cb) = ph;
                *(__nv_bfloat162*)(Clp + (size_t)r0o * ldc + cb) = pl;
                split_hl(v2, ph.x, pl.x); split_hl(v3, ph.y, pl.y);
                *(__nv_bfloat162*)(Chp + (size_t)r1o * ldc + cb) = ph;
                *(__nv_bfloat162*)(Clp + (size_t)r1o * ldc + cb) = pl;
            } else {
                float* p0 = Cp + (size_t)r0o * ldc + cb;
                float* p1 = Cp + (size_t)r1o * ldc + cb;
                if (EPI == 2) {
                    float2 o0 = *(const float2*)p0;
                    float2 o1 = *(const float2*)p1;
                    v0 += o0.x; v1 += o0.y; v2 += o1.x; v3 += o1.y;
                }
                *(float2*)p0 = make_float2(v0, v1);
                *(float2*)p1 = make_float2(v2, v3);
            }
        }
    }
}

// ----------------------------------------------------------------------------
// Attention (FFMA2). WHL=1 additionally emits bf16 hi/lo of the output.
// ----------------------------------------------------------------------------
template <int L, int WHL>
__global__ void attn_kernel(const float* __restrict__ qkv,
                            const float* __restrict__ cosT,
                            const float* __restrict__ sinT,
                            float* __restrict__ outp,
                            __nv_bfloat16* __restrict__ outh,
                            __nv_bfloat16* __restrict__ outl) {
    extern __shared__ float sm[];
    float* qr = sm;                 // 64*64
    float* kr = qr + 64 * 64;       // L*64
    float* vs = kr + L * 64;        // L*64
    float* sc = vs + L * 64;        // 64*L

    int batch = blockIdx.x;
    int h = blockIdx.y;
    int qc = blockIdx.z;
    int t = threadIdx.x;  // 256
    size_t base = (size_t)batch * L;
    const float* qkvb = qkv + base * 768;

    for (int idx = t; idx < L * 32; idx += 256) {
        int j = idx >> 5, d = idx & 31;
        const float* rowp = qkvb + (size_t)j * 768 + 256 + h * 64;
        float k1 = rowp[d], k2 = rowp[d + 32];
        float co = cosT[(j << 5) + d], si = sinT[(j << 5) + d];
        kr[(j << 6) + d]      = k1 * co - k2 * si;
        kr[(j << 6) + d + 32] = k1 * si + k2 * co;
    }
    for (int idx = t; idx < L * 64; idx += 256) {
        int j = idx >> 6, d = idx & 63;
        vs[idx] = qkvb[(size_t)j * 768 + 512 + h * 64 + d];
    }
    for (int idx = t; idx < 64 * 32; idx += 256) {
        int i = idx >> 5, d = idx & 31;
        int qi = qc * 64 + i;
        const float* rowp = qkvb + (size_t)qi * 768 + h * 64;
        float q1 = rowp[d], q2 = rowp[d + 32];
        float co = cosT[(qi << 5) + d], si = sinT[(qi << 5) + d];
        qr[(i << 6) + d]      = q1 * co - q2 * si;
        qr[(i << 6) + d + 32] = q1 * si + q2 * co;
    }
    __syncthreads();

    const int JP = L / 4;
    int i = t >> 2;
    int part = t & 3;

    unsigned long long q2r[32];
    {
        const ulonglong2* qrow = (const ulonglong2*)(qr + (i << 6));
#pragma unroll
        for (int u = 0; u < 16; u++) {
            ulonglong2 p = qrow[u];
            q2r[2 * u] = p.x;
            q2r[2 * u + 1] = p.y;
        }
    }

    float svals[JP];
    float mx = -1e30f;
#pragma unroll 4
    for (int jj = 0; jj < JP; jj++) {
        int j = part * JP + jj;
        const ulonglong2* krow = (const ulonglong2*)(kr + (j << 6));
        unsigned long long s2 = 0ull;
#pragma unroll
        for (int u = 0; u < 16; u++) {
            ulonglong2 kp = krow[u];
            s2 = fma2(q2r[2 * u], kp.x, s2);
            s2 = fma2(q2r[2 * u + 1], kp.y, s2);
        }
        float slo, shi;
        unpack2(s2, slo, shi);
        float s = (slo + shi) * 0.125f;
        svals[jj] = s;
        mx = fmaxf(mx, s);
    }
    mx = fmaxf(mx, __shfl_xor_sync(0xffffffffu, mx, 1));
    mx = fmaxf(mx, __shfl_xor_sync(0xffffffffu, mx, 2));
    float sum = 0.f;
#pragma unroll 4
    for (int jj = 0; jj < JP; jj++) {
        float e = __expf(svals[jj] - mx);
        svals[jj] = e;
        sum += e;
    }
    sum += __shfl_xor_sync(0xffffffffu, sum, 1);
    sum += __shfl_xor_sync(0xffffffffu, sum, 2);
    float invs = 1.0f / sum;
#pragma unroll 4
    for (int jj = 0; jj < JP; jj++) sc[i * L + part * JP + jj] = svals[jj] * invs;
    __syncthreads();

    int d0 = part << 4;
    unsigned long long acc2[8];
#pragma unroll
    for (int u = 0; u < 8; u++) acc2[u] = 0ull;
    for (int j = 0; j < L; j++) {
        unsigned long long pd = dup2(sc[i * L + j]);
        const ulonglong2* vrow = (const ulonglong2*)(vs + (j << 6) + d0);
#pragma unroll
        for (int u = 0; u < 4; u++) {
            ulonglong2 vp = vrow[u];
            acc2[2 * u] = fma2(pd, vp.x, acc2[2 * u]);
            acc2[2 * u + 1] = fma2(pd, vp.y, acc2[2 * u + 1]);
        }
    }
    size_t opidx = (base + (size_t)qc * 64 + i) * 256 + h * 64 + d0;
    float* op = outp + opidx;
#pragma unroll
    for (int u = 0; u < 4; u++) {
        float4 vv;
        unpack2(acc2[2 * u], vv.x, vv.y);
        unpack2(acc2[2 * u + 1], vv.z, vv.w);
        ((float4*)op)[u] = vv;
        if (WHL) {
            __nv_bfloat162 ph, pl;
            __nv_bfloat162* hp = (__nv_bfloat162*)(outh + opidx) + 2 * u;
            __nv_bfloat162* lp = (__nv_bfloat162*)(outl + opidx) + 2 * u;
            split_hl(vv.x, ph.x, pl.x); split_hl(vv.y, ph.y, pl.y);
            hp[0] = ph; lp[0] = pl;
            split_hl(vv.z, ph.x, pl.x); split_hl(vv.w, ph.y, pl.y);
            hp[1] = ph; lp[1] = pl;
        }
    }
}

// ----------------------------------------------------------------------------
// Launch
// ----------------------------------------------------------------------------
extern "C" void kernel_launch(void* const* d_in, const int* in_sizes, int n_in,
                              void* d_out, int out_size) {
    const float* src         = (const float*)d_in[0];
    const float* coords      = (const float*)d_in[1];
    const float* proj_attn_w = (const float*)d_in[4];
    const float* proj_attn_b = (const float*)d_in[5];
    const float* proj_ffn_w  = (const float*)d_in[8];
    const float* proj_ffn_b  = (const float*)d_in[9];
    const float* ln1_w = (const float*)d_in[10];
    const float* ln1_b = (const float*)d_in[11];
    const float* ln2_w = (const float*)d_in[12];
    const float* ln2_b = (const float*)d_in[13];
    const float* qkv_s_w = (const float*)d_in[14];
    const float* qkv_s_b = (const float*)d_in[15];
    const float* out_s_w = (const float*)d_in[16];
    const float* out_s_b = (const float*)d_in[17];
    const float* qkv_t_w = (const float*)d_in[18];
    const float* qkv_t_b = (const float*)d_in[19];
    const float* out_t_w = (const float*)d_in[20];
    const float* out_t_b = (const float*)d_in[21];
    const float* w1 = (const float*)d_in[22];
    const float* b1 = (const float*)d_in[23];
    const float* w2 = (const float*)d_in[24];
    const float* b2 = (const float*)d_in[25];
    float* out = (float*)d_out;

    float *scr0, *ln, *x2, *ao, *cs, *sn, *ct, *st;
    cudaGetSymbolAddress((void**)&scr0, g_scr0);
    cudaGetSymbolAddress((void**)&ln, g_ln);
    cudaGetSymbolAddress((void**)&x2, g_x2);
    cudaGetSymbolAddress((void**)&ao, g_ao);
    cudaGetSymbolAddress((void**)&cs, g_cos_s);
    cudaGetSymbolAddress((void**)&sn, g_sin_s);
    cudaGetSymbolAddress((void**)&ct, g_cos_t);
    cudaGetSymbolAddress((void**)&st, g_sin_t);
    __nv_bfloat16 *srch, *srcl, *lnh, *lnl, *x2h, *x2l, *aoh, *aol, *ffh, *ffl, *wh, *wl;
    cudaGetSymbolAddress((void**)&srch, g_srch);
    cudaGetSymbolAddress((void**)&srcl, g_srcl);
    cudaGetSymbolAddress((void**)&lnh, g_lnh);
    cudaGetSymbolAddress((void**)&lnl, g_lnl);
    cudaGetSymbolAddress((void**)&x2h, g_x2h);
    cudaGetSymbolAddress((void**)&x2l, g_x2l);
    cudaGetSymbolAddress((void**)&aoh, g_aoh);
    cudaGetSymbolAddress((void**)&aol, g_aol);
    cudaGetSymbolAddress((void**)&ffh, g_ffh);
    cudaGetSymbolAddress((void**)&ffl, g_ffl);
    cudaGetSymbolAddress((void**)&wh, g_wh);
    cudaGetSymbolAddress((void**)&wl, g_wl);

    const int smem64 = (64 * 64 + 64 * 64 * 2 + 64 * 64) * 4;
    const int smem128 = (64 * 64 + 128 * 64 * 2 + 64 * 128) * 4;
    const int smemMMA = 8 * 128 * 40 * 2;  // 81920
    cudaFuncSetAttribute((const void*)attn_kernel<64, 1>,
                         cudaFuncAttributeMaxDynamicSharedMemorySize, smem64);
    cudaFuncSetAttribute((const void*)attn_kernel<128, 1>,
                         cudaFuncAttributeMaxDynamicSharedMemorySize, smem128);
    cudaFuncSetAttribute((const void*)mma_gemm_kernel<0, 0, 0>,
                         cudaFuncAttributeMaxDynamicSharedMemorySize, smemMMA);
    cudaFuncSetAttribute((const void*)mma_gemm_kernel<1, 0, 0>,
                         cudaFuncAttributeMaxDynamicSharedMemorySize, smemMMA);
    cudaFuncSetAttribute((const void*)mma_gemm_kernel<2, 0, 0>,
                         cudaFuncAttributeMaxDynamicSharedMemorySize, smemMMA);
    cudaFuncSetAttribute((const void*)mma_gemm_kernel<0, 1, 0>,
                         cudaFuncAttributeMaxDynamicSharedMemorySize, smemMMA);
    cudaFuncSetAttribute((const void*)mma_gemm_kernel<2, 0, 1>,
                         cudaFuncAttributeMaxDynamicSharedMemorySize, smemMMA);

    // 0. rope tables + weight/src hi-lo conversion
    rope_setup_kernel<<<1, 128>>>(coords);
    convert_hl_kernel<<<256, 256>>>(proj_attn_w, wh + WOFF_PA, wl + WOFF_PA, DM * DM / 4);
    convert_hl_kernel<<<256, 256>>>(proj_ffn_w,  wh + WOFF_PF, wl + WOFF_PF, DM * DM / 4);
    convert_hl_kernel<<<256, 256>>>(qkv_t_w,     wh + WOFF_QT, wl + WOFF_QT, 768 * HALFD / 4);
    convert_hl_kernel<<<256, 256>>>(out_t_w,     wh + WOFF_OT, wl + WOFF_OT, HALFD * HALFD / 4);
    convert_hl_kernel<<<256, 256>>>(qkv_s_w,     wh + WOFF_QS, wl + WOFF_QS, 768 * HALFD / 4);
    convert_hl_kernel<<<256, 256>>>(out_s_w,     wh + WOFF_OS, wl + WOFF_OS, HALFD * HALFD / 4);
    convert_hl_kernel<<<1024, 256>>>(w1,         wh + WOFF_W1, wl + WOFF_W1, DFF * DM / 4);
    convert_hl_kernel<<<1024, 256>>>(w2,         wh + WOFF_W2, wl + WOFF_W2, DM * DFF / 4);
    convert_hl_kernel<<<4096, 256>>>(src, srch, srcl, NTOK * DM / 4);

    // 1. LN1: src -> g_ln (+ hi/lo)
    layernorm_kernel<<<NTOK, 128>>>(src, ln, lnh, lnl, ln1_w, ln1_b);

    // 2. res1 = src @ proj_attn_w^T + b -> g_x2   [tensor]
    mma_gemm_kernel<0, 0, 0><<<dim3(DM / 128, NTOK / 128), 256, smemMMA>>>(
        srch, srcl, DM, wh + WOFF_PA, wl + WOFF_PA, proj_attn_b,
        x2, nullptr, nullptr, DM, DM, DM);

    // 3. qkv_s = gather_spatial(ln[:, :256]) @ qkv_s_w^T + b -> scr0  [tensor, AMAP]
    mma_gemm_kernel<0, 1, 0><<<dim3(768 / 128, NTOK / 128), 256, smemMMA>>>(
        lnh, lnl, DM, wh + WOFF_QS, wl + WOFF_QS, qkv_s_b,
        scr0, nullptr, nullptr, 768, 768, HALFD);

    // 4. spatial attention -> g_ao (+ hi/lo)
    attn_kernel<64, 1><<<dim3(NB * NP, 4, 1), 256, smem64>>>(
        scr0, cs, sn, ao, aoh, aol);

    // 5. out-proj spatial: x2[:, :256] += scatter(ao @ out_s_w^T + b)  [tensor, CMAP]
    mma_gemm_kernel<2, 0, 1><<<dim3(HALFD / 128, NTOK / 128), 256, smemMMA>>>(
        aoh, aol, HALFD, wh + WOFF_OS, wl + WOFF_OS, out_s_b,
        x2, nullptr, nullptr, DM, HALFD, HALFD);

    // 6. qkv_t = ln[:, 256:] @ qkv_t_w^T + b -> scr0   [tensor]
    mma_gemm_kernel<0, 0, 0><<<dim3(768 / 128, NTOK / 128), 256, smemMMA>>>(
        lnh + HALFD, lnl + HALFD, DM, wh + WOFF_QT, wl + WOFF_QT, qkv_t_b,
        scr0, nullptr, nullptr, 768, 768, HALFD);

    // 7. temporal attention -> g_ao (+ hi/lo)
    attn_kernel<128, 1><<<dim3(NB * NC, 4, 2), 256, smem128>>>(
        scr0, ct, st, ao, aoh, aol);

    // 8. out-proj temporal: x2[:, 256:] += ao @ out_t_w^T + b   [tensor]
    mma_gemm_kernel<2, 0, 0><<<dim3(HALFD / 128, NTOK / 128), 256, smemMMA>>>(
        aoh, aol, HALFD, wh + WOFF_OT, wl + WOFF_OT, out_t_b,
        x2 + HALFD, nullptr, nullptr, DM, HALFD, HALFD);

    // 8b. convert x2 -> hi/lo (for step 10)
    convert_hl_kernel<<<4096, 256>>>(x2, x2h, x2l, NTOK * DM / 4);

    // 9. LN2: x2 -> g_ln (+ hi/lo)
    layernorm_kernel<<<NTOK, 128>>>(x2, ln, lnh, lnl, ln2_w, ln2_b);

    // 10. res2 = x2 @ proj_ffn_w^T + b -> out   [tensor]
    mma_gemm_kernel<0, 0, 0><<<dim3(DM / 128, NTOK / 128), 256, smemMMA>>>(
        x2h, x2l, DM, wh + WOFF_PF, wl + WOFF_PF, proj_ffn_b,
        out, nullptr, nullptr, DM, DM, DM);

    // 11. ffh/ffl = split(gelu(ln @ w1^T + b1))   [tensor, bf16 out]
    mma_gemm_kernel<1, 0, 0><<<dim3(DFF / 128, NTOK / 128), 256, smemMMA>>>(
        lnh, lnl, DM, wh + WOFF_W1, wl + WOFF_W1, b1,
        nullptr, ffh, ffl, DFF, DFF, DM);

    // 12. out += ff @ w2^T + b2   [tensor]
    mma_gemm_kernel<2, 0, 0><<<dim3(DM / 128, NTOK / 128), 256, smemMMA>>>(
        ffh, ffl, DFF, wh + WOFF_W2, wl + WOFF_W2, b2,
        out, nullptr, nullptr, DM, DM, DFF);
}